// round 1
// baseline (speedup 1.0000x reference)
#include <cuda_runtime.h>
#include <cuda_bf16.h>
#include <math.h>

#define BATCH 32
#define HW    1024
#define CDIM  256
#define FDIM  64

// ---------------- scratch (device globals; no allocations) ----------------
__device__ float g_emb[BATCH * HW * FDIM];        // 8 MB
__device__ float g_sq[BATCH * HW];
__device__ float g_T[BATCH * HW];
__device__ float g_shortcut[BATCH * HW * CDIM];   // 32 MB
__device__ float g_attn_Wt[CDIM * CDIM];          // attn_W transposed: [cin][cout]
__device__ float g_emb_Wt[CDIM * FDIM];           // emb_W transposed:  [cin][f]

// ---------------- prep: weight transposes ----------------
__global__ void prep_kernel(const float* __restrict__ attn_W,
                            const float* __restrict__ emb_W) {
    int t = blockIdx.x * 256 + threadIdx.x;
    if (t < CDIM * CDIM) {
        int co = t >> 8, ci = t & 255;
        g_attn_Wt[ci * CDIM + co] = attn_W[co * CDIM + ci];
    }
    if (t < FDIM * CDIM) {
        int f = t >> 8, ci = t & 255;
        g_emb_Wt[ci * FDIM + f] = emb_W[f * CDIM + ci];
    }
}

// ---------------- emb: x @ emb_W^T + b, plus row squared-norms ----------------
// 256 threads, 32 rows per block. smem: x tile 32KB + full transposed W 64KB.
#define EMB_SMEM ((32 * 256 + 256 * 64) * 4)
__global__ __launch_bounds__(256) void emb_kernel(const float* __restrict__ x,
                                                  const float* __restrict__ emb_b) {
    extern __shared__ float sm[];
    float* xs = sm;              // [32][256]
    float* we = sm + 32 * 256;   // [256][64] (cin-major)
    int tid = threadIdx.x;
    int row0 = blockIdx.x * 32;  // global flattened row b*HW+n

    const float4* xg = (const float4*)(x + (size_t)row0 * CDIM);
    float4* xs4 = (float4*)xs;
    for (int i = tid; i < 32 * 64; i += 256) xs4[i] = xg[i];
    const float4* wg = (const float4*)g_emb_Wt;
    float4* we4 = (float4*)we;
    for (int i = tid; i < 256 * 16; i += 256) we4[i] = wg[i];
    __syncthreads();

    int w = tid >> 5, lane = tid & 31;
    int ig = w * 4, fg = lane * 2;
    float acc[4][2] = {};
#pragma unroll 4
    for (int c = 0; c < 256; c++) {
        float2 wv = *(const float2*)&we[c * 64 + fg];
#pragma unroll
        for (int q = 0; q < 4; q++) {
            float a = xs[(ig + q) * 256 + c];
            acc[q][0] = fmaf(a, wv.x, acc[q][0]);
            acc[q][1] = fmaf(a, wv.y, acc[q][1]);
        }
    }
    float b0 = emb_b[fg], b1 = emb_b[fg + 1];
#pragma unroll
    for (int q = 0; q < 4; q++) {
        float e0 = acc[q][0] + b0, e1 = acc[q][1] + b1;
        int n = row0 + ig + q;
        *(float2*)&g_emb[(size_t)n * FDIM + fg] = make_float2(e0, e1);
        float p = e0 * e0 + e1 * e1;
#pragma unroll
        for (int o = 16; o; o >>= 1) p += __shfl_xor_sync(0xffffffffu, p, o);
        if (lane == 0) g_sq[n] = p;
    }
}

// ---------------- shortcut: x @ attn_W^T + b, plus threshold T ----------------
// 256 threads, 32 rows per block, 4x8 register tile. smem 64KB.
#define SC_SMEM ((32 * 256 * 2) * 4)
__global__ __launch_bounds__(256) void shortcut_kernel(const float* __restrict__ x,
                                                       const float* __restrict__ attn_b,
                                                       const float* __restrict__ thr_W,
                                                       const float* __restrict__ thr_b) {
    extern __shared__ float sm[];
    float* xs = sm;             // [32][256]
    float* wt = sm + 32 * 256;  // [32][256] chunk of transposed W
    int tid = threadIdx.x;
    int row0 = blockIdx.x * 32;

    const float4* xg = (const float4*)(x + (size_t)row0 * CDIM);
    float4* xs4 = (float4*)xs;
    for (int i = tid; i < 2048; i += 256) xs4[i] = xg[i];

    int w = tid >> 5, lane = tid & 31;
    int ig = w * 4, cg = lane * 8;
    float acc[4][8] = {};
    for (int kc = 0; kc < 8; kc++) {
        __syncthreads();
        const float4* wg = (const float4*)(g_attn_Wt + kc * 32 * CDIM);
        float4* wt4 = (float4*)wt;
        for (int i = tid; i < 2048; i += 256) wt4[i] = wg[i];
        __syncthreads();
#pragma unroll 4
        for (int kk = 0; kk < 32; kk++) {
            float4 w0 = *(float4*)&wt[kk * 256 + cg];
            float4 w1 = *(float4*)&wt[kk * 256 + cg + 4];
#pragma unroll
            for (int q = 0; q < 4; q++) {
                float a = xs[(ig + q) * 256 + kc * 32 + kk];
                acc[q][0] = fmaf(a, w0.x, acc[q][0]);
                acc[q][1] = fmaf(a, w0.y, acc[q][1]);
                acc[q][2] = fmaf(a, w0.z, acc[q][2]);
                acc[q][3] = fmaf(a, w0.w, acc[q][3]);
                acc[q][4] = fmaf(a, w1.x, acc[q][4]);
                acc[q][5] = fmaf(a, w1.y, acc[q][5]);
                acc[q][6] = fmaf(a, w1.z, acc[q][6]);
                acc[q][7] = fmaf(a, w1.w, acc[q][7]);
            }
        }
    }
    float4 bb0 = *(const float4*)&attn_b[cg];
    float4 bb1 = *(const float4*)&attn_b[cg + 4];
    float4 tw0 = *(const float4*)&thr_W[cg];
    float4 tw1 = *(const float4*)&thr_W[cg + 4];
    float thrb = thr_b[0];
#pragma unroll
    for (int q = 0; q < 4; q++) {
        float4 o0, o1;
        o0.x = acc[q][0] + bb0.x; o0.y = acc[q][1] + bb0.y;
        o0.z = acc[q][2] + bb0.z; o0.w = acc[q][3] + bb0.w;
        o1.x = acc[q][4] + bb1.x; o1.y = acc[q][5] + bb1.y;
        o1.z = acc[q][6] + bb1.z; o1.w = acc[q][7] + bb1.w;
        int n = row0 + ig + q;
        *(float4*)&g_shortcut[(size_t)n * CDIM + cg] = o0;
        *(float4*)&g_shortcut[(size_t)n * CDIM + cg + 4] = o1;
        float tp = o0.x * tw0.x + o0.y * tw0.y + o0.z * tw0.z + o0.w * tw0.w +
                   o1.x * tw1.x + o1.y * tw1.y + o1.z * tw1.z + o1.w * tw1.w;
#pragma unroll
        for (int o = 16; o; o >>= 1) tp += __shfl_xor_sync(0xffffffffu, tp, o);
        if (lane == 0) g_T[n] = tp + thrb;
    }
}

// ---------------- fused attention kernel ----------------
// One CTA per (batch, 32-row tile). S[32][1024] resident in smem.
#define AS_EIT (32 * 1024)
#define AS_U   (AS_EIT + 64 * 32)
#define AS_TS  (AS_U + 64 * 132)    // union region: max(Ejt 64*132, SC 32*256)
#define AS_SQJ (AS_TS + 1024)
#define AS_SQI (AS_SQJ + 1024)
#define ATTN_SMEM_FLOATS (AS_SQI + 32)
#define ATTN_SMEM (ATTN_SMEM_FLOATS * 4)

__global__ __launch_bounds__(256) void attn_kernel(const float* __restrict__ x,
                                                   float* __restrict__ out) {
    extern __shared__ float sm[];
    float* S   = sm;             // [32][1024] : s -> e -> u -> p
    float* Eit = sm + AS_EIT;    // [k=64][i=32]
    float* U   = sm + AS_U;      // union: Ejt [k=64][j pad 132]  /  SC [32][256]
    float* Tsh = sm + AS_TS;     // [1024]
    float* Sqj = sm + AS_SQJ;    // [1024]
    float* Sqi = sm + AS_SQI;    // [32]

    int tid = threadIdx.x;
    int tile = blockIdx.x, b = blockIdx.y;
    int i0 = tile * 32;
    int base = b * HW;

    for (int i = tid; i < 1024; i += 256) {
        Tsh[i] = g_T[base + i];
        Sqj[i] = g_sq[base + i];
    }
    if (tid < 32) Sqi[tid] = g_sq[base + i0 + tid];
    for (int idx = tid; idx < 32 * 64; idx += 256) {
        int i = idx >> 6, k = idx & 63;
        Eit[k * 32 + i] = g_emb[(size_t)(base + i0 + i) * FDIM + k];
    }

    int w = tid >> 5, lane = tid & 31;
    int ig = w * 4, jgl = lane * 4;

    int yi[4], xi[4];
#pragma unroll
    for (int q = 0; q < 4; q++) {
        int ni = i0 + ig + q;
        yi[q] = ni >> 5; xi[q] = ni & 31;
    }

    // ---- Phase A: Gram + attention logits s ----
    for (int jc = 0; jc < 8; jc++) {
        __syncthreads();
        for (int idx = tid; idx < 128 * 64; idx += 256) {
            int j = idx >> 6, k = idx & 63;
            U[k * 132 + j] = g_emb[(size_t)(base + jc * 128 + j) * FDIM + k];
        }
        __syncthreads();
        float acc[4][4] = {};
#pragma unroll 8
        for (int k = 0; k < 64; k++) {
            float4 a = *(float4*)&Eit[k * 32 + ig];
            float4 bb = *(float4*)&U[k * 132 + jgl];
            acc[0][0] = fmaf(a.x, bb.x, acc[0][0]); acc[0][1] = fmaf(a.x, bb.y, acc[0][1]);
            acc[0][2] = fmaf(a.x, bb.z, acc[0][2]); acc[0][3] = fmaf(a.x, bb.w, acc[0][3]);
            acc[1][0] = fmaf(a.y, bb.x, acc[1][0]); acc[1][1] = fmaf(a.y, bb.y, acc[1][1]);
            acc[1][2] = fmaf(a.y, bb.z, acc[1][2]); acc[1][3] = fmaf(a.y, bb.w, acc[1][3]);
            acc[2][0] = fmaf(a.z, bb.x, acc[2][0]); acc[2][1] = fmaf(a.z, bb.y, acc[2][1]);
            acc[2][2] = fmaf(a.z, bb.z, acc[2][2]); acc[2][3] = fmaf(a.z, bb.w, acc[2][3]);
            acc[3][0] = fmaf(a.w, bb.x, acc[3][0]); acc[3][1] = fmaf(a.w, bb.y, acc[3][1]);
            acc[3][2] = fmaf(a.w, bb.z, acc[3][2]); acc[3][3] = fmaf(a.w, bb.w, acc[3][3]);
        }
#pragma unroll
        for (int q = 0; q < 4; q++) {
            float4 sv;
            float sqi = Sqi[ig + q];
            float* svp = &sv.x;
#pragma unroll
            for (int qq = 0; qq < 4; qq++) {
                int j = jc * 128 + jgl + qq;
                float d2 = fmaxf(sqi + Sqj[j] - 2.0f * acc[q][qq], 0.0f);
                int yj = j >> 5, xj = j & 31;
                int diff = abs(yi[q] - yj) + abs(xi[q] - xj);
                float mask = (diff <= 32) ? (float)diff * (1.0f / 32.0f) : 0.0f;
                svp[qq] = __expf(-d2) - 1.0f + mask;
            }
            *(float4*)&S[(ig + q) * 1024 + jc * 128 + jgl] = sv;
        }
    }
    __syncwarp();  // phase A lanes wrote jgl-pattern; phase B reads lane-pattern (same warp)

    // ---- Phase B: double softmax, warp-local rows ----
    float inv2r[4];
#pragma unroll
    for (int q = 0; q < 4; q++) {
        float* Sr = S + (ig + q) * 1024;
        float m = -1e30f;
#pragma unroll 8
        for (int t = 0; t < 32; t++) m = fmaxf(m, Sr[lane + t * 32]);
#pragma unroll
        for (int o = 16; o; o >>= 1) m = fmaxf(m, __shfl_xor_sync(0xffffffffu, m, o));
        float s1 = 0.0f;
#pragma unroll 8
        for (int t = 0; t < 32; t++) {
            int j = lane + t * 32;
            float e = __expf(Sr[j] - m);
            Sr[j] = e;
            s1 += e;
        }
#pragma unroll
        for (int o = 16; o; o >>= 1) s1 += __shfl_xor_sync(0xffffffffu, s1, o);
        float inv1 = 1.0f / s1;
        float m2 = 0.0f;
#pragma unroll 8
        for (int t = 0; t < 32; t++) {
            int j = lane + t * 32;
            float u = fmaxf(Sr[j] * inv1 - Tsh[j], 0.0f);
            Sr[j] = u;
            m2 = fmaxf(m2, u);
        }
#pragma unroll
        for (int o = 16; o; o >>= 1) m2 = fmaxf(m2, __shfl_xor_sync(0xffffffffu, m2, o));
        float s2 = 0.0f;
#pragma unroll 8
        for (int t = 0; t < 32; t++) {
            int j = lane + t * 32;
            float p = __expf(Sr[j] - m2);
            Sr[j] = p;
            s2 += p;
        }
#pragma unroll
        for (int o = 16; o; o >>= 1) s2 += __shfl_xor_sync(0xffffffffu, s2, o);
        inv2r[q] = 1.0f / s2;
    }

    // ---- Phase C: attn_out = A @ shortcut ----
    int cg = lane * 8;
    float acc[4][8] = {};
    for (int jc = 0; jc < 32; jc++) {
        __syncthreads();
        const float4* sg = (const float4*)(g_shortcut + (size_t)(base + jc * 32) * CDIM);
        float4* U4 = (float4*)U;
        for (int i2 = tid; i2 < 2048; i2 += 256) U4[i2] = sg[i2];
        __syncthreads();
#pragma unroll 4
        for (int jj = 0; jj < 32; jj++) {
            float4 s0 = *(float4*)&U[jj * 256 + cg];
            float4 s1 = *(float4*)&U[jj * 256 + cg + 4];
#pragma unroll
            for (int q = 0; q < 4; q++) {
                float a = S[(ig + q) * 1024 + jc * 32 + jj];
                acc[q][0] = fmaf(a, s0.x, acc[q][0]);
                acc[q][1] = fmaf(a, s0.y, acc[q][1]);
                acc[q][2] = fmaf(a, s0.z, acc[q][2]);
                acc[q][3] = fmaf(a, s0.w, acc[q][3]);
                acc[q][4] = fmaf(a, s1.x, acc[q][4]);
                acc[q][5] = fmaf(a, s1.y, acc[q][5]);
                acc[q][6] = fmaf(a, s1.z, acc[q][6]);
                acc[q][7] = fmaf(a, s1.w, acc[q][7]);
            }
        }
    }
    // epilogue: out = x + attn_out / l2
#pragma unroll
    for (int q = 0; q < 4; q++) {
        size_t n = (size_t)(base + i0 + ig + q);
        float inv = inv2r[q];
        float4 xv0 = *(const float4*)&x[n * CDIM + cg];
        float4 xv1 = *(const float4*)&x[n * CDIM + cg + 4];
        float4 o0, o1;
        o0.x = xv0.x + acc[q][0] * inv; o0.y = xv0.y + acc[q][1] * inv;
        o0.z = xv0.z + acc[q][2] * inv; o0.w = xv0.w + acc[q][3] * inv;
        o1.x = xv1.x + acc[q][4] * inv; o1.y = xv1.y + acc[q][5] * inv;
        o1.z = xv1.z + acc[q][6] * inv; o1.w = xv1.w + acc[q][7] * inv;
        *(float4*)&out[n * CDIM + cg] = o0;
        *(float4*)&out[n * CDIM + cg + 4] = o1;
    }
}

// ---------------- launch ----------------
extern "C" void kernel_launch(void* const* d_in, const int* in_sizes, int n_in,
                              void* d_out, int out_size) {
    const float* x      = (const float*)d_in[0];
    const float* emb_W  = (const float*)d_in[1];
    const float* emb_b  = (const float*)d_in[2];
    const float* attn_W = (const float*)d_in[3];
    const float* attn_b = (const float*)d_in[4];
    const float* thr_W  = (const float*)d_in[5];
    const float* thr_b  = (const float*)d_in[6];
    float* out = (float*)d_out;

    cudaFuncSetAttribute(emb_kernel, cudaFuncAttributeMaxDynamicSharedMemorySize, EMB_SMEM);
    cudaFuncSetAttribute(shortcut_kernel, cudaFuncAttributeMaxDynamicSharedMemorySize, SC_SMEM);
    cudaFuncSetAttribute(attn_kernel, cudaFuncAttributeMaxDynamicSharedMemorySize, ATTN_SMEM);

    prep_kernel<<<256, 256>>>(attn_W, emb_W);
    emb_kernel<<<BATCH * HW / 32, 256, EMB_SMEM>>>(x, emb_b);
    shortcut_kernel<<<BATCH * HW / 32, 256, SC_SMEM>>>(x, attn_b, thr_W, thr_b);
    attn_kernel<<<dim3(HW / 32, BATCH), 256, ATTN_SMEM>>>(x, out);
}

// round 3
// speedup vs baseline: 1.8137x; 1.8137x over previous
#include <cuda_runtime.h>
#include <cuda_bf16.h>
#include <math.h>
#include <stdint.h>

#define BATCH 32
#define HW    1024
#define CDIM  256
#define FDIM  64

// ---------------- scratch (device globals; no allocations) ----------------
__device__ float g_emb[BATCH * HW * FDIM];              // 8 MB
__device__ float g_sq[BATCH * HW];
__device__ float g_T[BATCH * HW];
__device__ __nv_bfloat16 g_SChi[BATCH * HW * CDIM];     // 16 MB
__device__ __nv_bfloat16 g_SClo[BATCH * HW * CDIM];     // 16 MB
__device__ __nv_bfloat16 g_Ahi[(size_t)BATCH * HW * HW]; // 64 MB
__device__ __nv_bfloat16 g_Alo[(size_t)BATCH * HW * HW]; // 64 MB
__device__ float g_attn_Wt[CDIM * CDIM];
__device__ float g_emb_Wt[CDIM * FDIM];

// ---------------- small helpers ----------------
__device__ __forceinline__ uint32_t smem_u32(const void* p) {
    return (uint32_t)__cvta_generic_to_shared(p);
}
__device__ __forceinline__ void cp16(uint32_t dst, const void* src) {
    asm volatile("cp.async.cg.shared.global [%0], [%1], 16;\n" :: "r"(dst), "l"(src));
}
__device__ __forceinline__ void ldm_x4(uint32_t (&r)[4], uint32_t addr) {
    asm volatile("ldmatrix.sync.aligned.m8n8.x4.shared.b16 {%0,%1,%2,%3}, [%4];"
                 : "=r"(r[0]), "=r"(r[1]), "=r"(r[2]), "=r"(r[3]) : "r"(addr));
}
__device__ __forceinline__ void ldm_x4_t(uint32_t (&r)[4], uint32_t addr) {
    asm volatile("ldmatrix.sync.aligned.m8n8.x4.trans.shared.b16 {%0,%1,%2,%3}, [%4];"
                 : "=r"(r[0]), "=r"(r[1]), "=r"(r[2]), "=r"(r[3]) : "r"(addr));
}
__device__ __forceinline__ void mma16816(float (&d)[4], const uint32_t (&a)[4],
                                         uint32_t b0, uint32_t b1) {
    asm volatile("mma.sync.aligned.m16n8k16.row.col.f32.bf16.bf16.f32 "
                 "{%0,%1,%2,%3}, {%4,%5,%6,%7}, {%8,%9}, {%0,%1,%2,%3};"
                 : "+f"(d[0]), "+f"(d[1]), "+f"(d[2]), "+f"(d[3])
                 : "r"(a[0]), "r"(a[1]), "r"(a[2]), "r"(a[3]), "r"(b0), "r"(b1));
}

// ---------------- prep: weight transposes ----------------
__global__ void prep_kernel(const float* __restrict__ attn_W,
                            const float* __restrict__ emb_W) {
    int t = blockIdx.x * 256 + threadIdx.x;
    if (t < CDIM * CDIM) {
        int co = t >> 8, ci = t & 255;
        g_attn_Wt[ci * CDIM + co] = attn_W[co * CDIM + ci];
    }
    if (t < FDIM * CDIM) {
        int f = t >> 8, ci = t & 255;
        g_emb_Wt[ci * FDIM + f] = emb_W[f * CDIM + ci];
    }
}

// ---------------- emb: x @ emb_W^T + b, plus row squared-norms ----------------
#define EMB_SMEM ((32 * 256 + 256 * 64) * 4)
__global__ __launch_bounds__(256) void emb_kernel(const float* __restrict__ x,
                                                  const float* __restrict__ emb_b) {
    extern __shared__ float sm[];
    float* xs = sm;              // [32][256]
    float* we = sm + 32 * 256;   // [256][64]
    int tid = threadIdx.x;
    int row0 = blockIdx.x * 32;

    const float4* xg = (const float4*)(x + (size_t)row0 * CDIM);
    float4* xs4 = (float4*)xs;
    for (int i = tid; i < 32 * 64; i += 256) xs4[i] = xg[i];
    const float4* wg = (const float4*)g_emb_Wt;
    float4* we4 = (float4*)we;
    for (int i = tid; i < 256 * 16; i += 256) we4[i] = wg[i];
    __syncthreads();

    int w = tid >> 5, lane = tid & 31;
    int ig = w * 4, fg = lane * 2;
    float acc[4][2] = {};
#pragma unroll 4
    for (int c = 0; c < 256; c++) {
        float2 wv = *(const float2*)&we[c * 64 + fg];
#pragma unroll
        for (int q = 0; q < 4; q++) {
            float a = xs[(ig + q) * 256 + c];
            acc[q][0] = fmaf(a, wv.x, acc[q][0]);
            acc[q][1] = fmaf(a, wv.y, acc[q][1]);
        }
    }
    float b0 = emb_b[fg], b1 = emb_b[fg + 1];
#pragma unroll
    for (int q = 0; q < 4; q++) {
        float e0 = acc[q][0] + b0, e1 = acc[q][1] + b1;
        int n = row0 + ig + q;
        *(float2*)&g_emb[(size_t)n * FDIM + fg] = make_float2(e0, e1);
        float p = e0 * e0 + e1 * e1;
#pragma unroll
        for (int o = 16; o; o >>= 1) p += __shfl_xor_sync(0xffffffffu, p, o);
        if (lane == 0) g_sq[n] = p;
    }
}

// ---------------- shortcut: x @ attn_W^T + b -> bf16 hi/lo, plus threshold T ----------------
#define SC_SMEM ((32 * 256 * 2) * 4)
__global__ __launch_bounds__(256) void shortcut_kernel(const float* __restrict__ x,
                                                       const float* __restrict__ attn_b,
                                                       const float* __restrict__ thr_W,
                                                       const float* __restrict__ thr_b) {
    extern __shared__ float sm[];
    float* xs = sm;             // [32][256]
    float* wt = sm + 32 * 256;  // [32][256] chunk of Wt
    int tid = threadIdx.x;
    int row0 = blockIdx.x * 32;

    const float4* xg = (const float4*)(x + (size_t)row0 * CDIM);
    float4* xs4 = (float4*)xs;
    for (int i = tid; i < 2048; i += 256) xs4[i] = xg[i];

    int w = tid >> 5, lane = tid & 31;
    int ig = w * 4, cg = lane * 8;
    float acc[4][8] = {};
    for (int kc = 0; kc < 8; kc++) {
        __syncthreads();
        const float4* wg = (const float4*)(g_attn_Wt + kc * 32 * CDIM);
        float4* wt4 = (float4*)wt;
        for (int i = tid; i < 2048; i += 256) wt4[i] = wg[i];
        __syncthreads();
#pragma unroll 4
        for (int kk = 0; kk < 32; kk++) {
            float4 w0 = *(float4*)&wt[kk * 256 + cg];
            float4 w1 = *(float4*)&wt[kk * 256 + cg + 4];
#pragma unroll
            for (int q = 0; q < 4; q++) {
                float a = xs[(ig + q) * 256 + kc * 32 + kk];
                acc[q][0] = fmaf(a, w0.x, acc[q][0]);
                acc[q][1] = fmaf(a, w0.y, acc[q][1]);
                acc[q][2] = fmaf(a, w0.z, acc[q][2]);
                acc[q][3] = fmaf(a, w0.w, acc[q][3]);
                acc[q][4] = fmaf(a, w1.x, acc[q][4]);
                acc[q][5] = fmaf(a, w1.y, acc[q][5]);
                acc[q][6] = fmaf(a, w1.z, acc[q][6]);
                acc[q][7] = fmaf(a, w1.w, acc[q][7]);
            }
        }
    }
    float4 bb0 = *(const float4*)&attn_b[cg];
    float4 bb1 = *(const float4*)&attn_b[cg + 4];
    float4 tw0 = *(const float4*)&thr_W[cg];
    float4 tw1 = *(const float4*)&thr_W[cg + 4];
    float thrb = thr_b[0];
#pragma unroll
    for (int q = 0; q < 4; q++) {
        float v[8];
        v[0] = acc[q][0] + bb0.x; v[1] = acc[q][1] + bb0.y;
        v[2] = acc[q][2] + bb0.z; v[3] = acc[q][3] + bb0.w;
        v[4] = acc[q][4] + bb1.x; v[5] = acc[q][5] + bb1.y;
        v[6] = acc[q][6] + bb1.z; v[7] = acc[q][7] + bb1.w;
        int n = row0 + ig + q;
        size_t off = (size_t)n * CDIM + cg;
        // hi/lo bf16 split stores (16B each)
        union { __nv_bfloat16 h[8]; uint4 u; } ph, pl;
#pragma unroll
        for (int i2 = 0; i2 < 8; i2++) {
            __nv_bfloat16 h = __float2bfloat16(v[i2]);
            ph.h[i2] = h;
            pl.h[i2] = __float2bfloat16(v[i2] - __bfloat162float(h));
        }
        *(uint4*)&g_SChi[off] = ph.u;
        *(uint4*)&g_SClo[off] = pl.u;
        float tp = v[0] * tw0.x + v[1] * tw0.y + v[2] * tw0.z + v[3] * tw0.w +
                   v[4] * tw1.x + v[5] * tw1.y + v[6] * tw1.z + v[7] * tw1.w;
#pragma unroll
        for (int o = 16; o; o >>= 1) tp += __shfl_xor_sync(0xffffffffu, tp, o);
        if (lane == 0) g_T[n] = tp + thrb;
    }
}

// ---------------- attention matrix kernel (phases A+B, writes A hi/lo) ----------------
#define UPITCH 134
#define AS_EIT (32 * 1024)
#define AS_U   (AS_EIT + 64 * 32)
#define AS_TS  (AS_U + 64 * UPITCH)
#define AS_SQJ (AS_TS + 1024)
#define AS_SQI (AS_SQJ + 1024)
#define ATTN_SMEM_FLOATS (AS_SQI + 32)
#define ATTN_SMEM (ATTN_SMEM_FLOATS * 4)

__global__ __launch_bounds__(512) void attn_A_kernel() {
    extern __shared__ float sm[];
    float* S   = sm;             // [32][1024]
    float* Eit = sm + AS_EIT;    // [k=64][i=32]
    float* U   = sm + AS_U;      // Ejt [k=64][j pad 134]
    float* Tsh = sm + AS_TS;     // [1024]
    float* Sqj = sm + AS_SQJ;    // [1024]
    float* Sqi = sm + AS_SQI;    // [32]

    int tid = threadIdx.x;
    int tile = blockIdx.x, b = blockIdx.y;
    int i0 = tile * 32;
    int base = b * HW;

    for (int i = tid; i < 1024; i += 512) {
        Tsh[i] = g_T[base + i];
        Sqj[i] = g_sq[base + i];
    }
    if (tid < 32) Sqi[tid] = g_sq[base + i0 + tid];
    for (int idx = tid; idx < 32 * 64; idx += 512) {
        int i = idx >> 6, k = idx & 63;
        Eit[k * 32 + i] = g_emb[(size_t)(base + i0 + i) * FDIM + k];
    }

    int w = tid >> 5, lane = tid & 31;
    int rowg = (w >> 1) * 4;           // warp pair owns 4 rows
    int jh = w & 1;                    // which half of the 128-j chunk
    int jloc = jh * 64 + lane * 2;

    int yi[4], xi[4];
#pragma unroll
    for (int q = 0; q < 4; q++) {
        int ni = i0 + rowg + q;
        yi[q] = ni >> 5; xi[q] = ni & 31;
    }

    // ---- Phase A: Gram + logits s ----
    for (int jc = 0; jc < 8; jc++) {
        __syncthreads();
        for (int idx = tid; idx < 128 * 64; idx += 512) {
            int j = idx >> 6, k = idx & 63;
            U[k * UPITCH + j] = g_emb[(size_t)(base + jc * 128 + j) * FDIM + k];
        }
        __syncthreads();
        float acc[4][2] = {};
#pragma unroll 8
        for (int k = 0; k < 64; k++) {
            float4 a = *(float4*)&Eit[k * 32 + rowg];
            float2 bb = *(float2*)&U[k * UPITCH + jloc];
            acc[0][0] = fmaf(a.x, bb.x, acc[0][0]); acc[0][1] = fmaf(a.x, bb.y, acc[0][1]);
            acc[1][0] = fmaf(a.y, bb.x, acc[1][0]); acc[1][1] = fmaf(a.y, bb.y, acc[1][1]);
            acc[2][0] = fmaf(a.z, bb.x, acc[2][0]); acc[2][1] = fmaf(a.z, bb.y, acc[2][1]);
            acc[3][0] = fmaf(a.w, bb.x, acc[3][0]); acc[3][1] = fmaf(a.w, bb.y, acc[3][1]);
        }
#pragma unroll
        for (int q = 0; q < 4; q++) {
            float sqi = Sqi[rowg + q];
            float2 sv;
            float* svp = &sv.x;
#pragma unroll
            for (int qq = 0; qq < 2; qq++) {
                int j = jc * 128 + jloc + qq;
                float d2 = fmaxf(sqi + Sqj[j] - 2.0f * acc[q][qq], 0.0f);
                int yj = j >> 5, xj = j & 31;
                int diff = abs(yi[q] - yj) + abs(xi[q] - xj);
                float mask = (diff <= 32) ? (float)diff * (1.0f / 32.0f) : 0.0f;
                svp[qq] = __expf(-d2) - 1.0f + mask;
            }
            *(float2*)&S[(rowg + q) * 1024 + jc * 128 + jloc] = sv;
        }
    }
    __syncthreads();   // cross-warp: phase A pair-pattern -> phase B row-pattern

    // ---- Phase B: double softmax + store A (hi/lo bf16, inv2 folded) ----
#pragma unroll
    for (int q = 0; q < 2; q++) {
        int r = w * 2 + q;
        float* Sr = S + r * 1024;
        float m = -1e30f;
#pragma unroll 8
        for (int t = 0; t < 32; t++) m = fmaxf(m, Sr[lane + t * 32]);
#pragma unroll
        for (int o = 16; o; o >>= 1) m = fmaxf(m, __shfl_xor_sync(0xffffffffu, m, o));
        float s1 = 0.0f;
#pragma unroll 8
        for (int t = 0; t < 32; t++) {
            int j = lane + t * 32;
            float e = __expf(Sr[j] - m);
            Sr[j] = e;
            s1 += e;
        }
#pragma unroll
        for (int o = 16; o; o >>= 1) s1 += __shfl_xor_sync(0xffffffffu, s1, o);
        float inv1 = 1.0f / s1;
        float m2 = 0.0f;
#pragma unroll 8
        for (int t = 0; t < 32; t++) {
            int j = lane + t * 32;
            float u = fmaxf(Sr[j] * inv1 - Tsh[j], 0.0f);
            Sr[j] = u;
            m2 = fmaxf(m2, u);
        }
#pragma unroll
        for (int o = 16; o; o >>= 1) m2 = fmaxf(m2, __shfl_xor_sync(0xffffffffu, m2, o));
        float s2 = 0.0f;
#pragma unroll 8
        for (int t = 0; t < 32; t++) {
            int j = lane + t * 32;
            float p = __expf(Sr[j] - m2);
            Sr[j] = p;
            s2 += p;
        }
#pragma unroll
        for (int o = 16; o; o >>= 1) s2 += __shfl_xor_sync(0xffffffffu, s2, o);
        float inv2 = 1.0f / s2;

        size_t Ab = ((size_t)b << 20) + (size_t)(i0 + r) * 1024;
#pragma unroll 8
        for (int t = 0; t < 32; t++) {
            int j = lane + t * 32;
            float val = Sr[j] * inv2;
            __nv_bfloat16 h = __float2bfloat16(val);
            g_Ahi[Ab + j] = h;
            g_Alo[Ab + j] = __float2bfloat16(val - __bfloat162float(h));
        }
    }
}

// ---------------- tensor-core bmm: out = x + A @ SC (3-term bf16 split) ----------------
__global__ __launch_bounds__(256) void bmm_kernel(const float* __restrict__ x,
                                                  float* __restrict__ out) {
    __shared__ __nv_bfloat16 As[2][128][40];   // 20 KB
    __shared__ __nv_bfloat16 Ss[2][32][136];   // 17 KB
    int tid = threadIdx.x, w = tid >> 5, lane = tid & 31;
    int ct = blockIdx.x, mt = blockIdx.y, b = blockIdx.z;
    int i0 = mt * 128, c0 = ct * 128;

    const __nv_bfloat16* Ahi = g_Ahi + ((size_t)b << 20) + (size_t)i0 * 1024;
    const __nv_bfloat16* Alo = g_Alo + ((size_t)b << 20) + (size_t)i0 * 1024;
    const __nv_bfloat16* Shi = g_SChi + ((size_t)b << 18) + c0;
    const __nv_bfloat16* Slo = g_SClo + ((size_t)b << 18) + c0;

    float acc[4][4][4];
#pragma unroll
    for (int a = 0; a < 4; a++)
#pragma unroll
        for (int n = 0; n < 4; n++)
#pragma unroll
            for (int r = 0; r < 4; r++) acc[a][n][r] = 0.0f;

    int wm = w >> 2, wn = w & 3;
    int lrow = lane & 7, q1 = (lane >> 3) & 1, q2 = lane >> 4;

    // precomputed load coords
    int ar0 = tid >> 2, aseg = tid & 3;          // A rows (2 reps of 256)
    int sr0 = tid >> 4, sseg = tid & 15;         // S rows

#define ISSUE(cc)                                                                 \
    {                                                                             \
        int term_ = (cc) >> 5, jc_ = (cc) & 31, buf_ = (cc) & 1;                  \
        const __nv_bfloat16* Ap_ = (term_ == 1) ? Alo : Ahi;                      \
        const __nv_bfloat16* Sp_ = (term_ == 2) ? Slo : Shi;                      \
        cp16(smem_u32(&As[buf_][ar0][aseg * 8]),                                  \
             Ap_ + (size_t)ar0 * 1024 + jc_ * 32 + aseg * 8);                     \
        cp16(smem_u32(&As[buf_][ar0 + 64][aseg * 8]),                             \
             Ap_ + (size_t)(ar0 + 64) * 1024 + jc_ * 32 + aseg * 8);              \
        cp16(smem_u32(&Ss[buf_][sr0][sseg * 8]),                                  \
             Sp_ + (size_t)(jc_ * 32 + sr0) * 256 + sseg * 8);                    \
        cp16(smem_u32(&Ss[buf_][sr0 + 16][sseg * 8]),                             \
             Sp_ + (size_t)(jc_ * 32 + sr0 + 16) * 256 + sseg * 8);               \
        asm volatile("cp.async.commit_group;\n");                                 \
    }

    ISSUE(0);
    for (int cc = 0; cc < 96; cc++) {
        if (cc < 95) {
            ISSUE(cc + 1);
            asm volatile("cp.async.wait_group 1;\n");
        } else {
            asm volatile("cp.async.wait_group 0;\n");
        }
        __syncthreads();
        int buf = cc & 1;
#pragma unroll
        for (int kk = 0; kk < 2; kk++) {
            uint32_t af[4][4];
#pragma unroll
            for (int mtl = 0; mtl < 4; mtl++) {
                int row = wm * 64 + mtl * 16 + lrow + q1 * 8;
                int col = kk * 16 + q2 * 8;
                ldm_x4(af[mtl], smem_u32(&As[buf][row][col]));
            }
            uint32_t bfr[2][4];
#pragma unroll
            for (int ng = 0; ng < 2; ng++) {
                int row = kk * 16 + lrow + q1 * 8;
                int col = wn * 32 + ng * 16 + q2 * 8;
                ldm_x4_t(bfr[ng], smem_u32(&Ss[buf][row][col]));
            }
#pragma unroll
            for (int mtl = 0; mtl < 4; mtl++)
#pragma unroll
                for (int nt = 0; nt < 4; nt++)
                    mma16816(acc[mtl][nt], af[mtl],
                             bfr[nt >> 1][(nt & 1) * 2], bfr[nt >> 1][(nt & 1) * 2 + 1]);
        }
        __syncthreads();
    }
#undef ISSUE

    // epilogue: out = x + acc
    int g = lane >> 2, t2 = lane & 3;
#pragma unroll
    for (int mtl = 0; mtl < 4; mtl++) {
#pragma unroll
        for (int nt = 0; nt < 4; nt++) {
            int row = i0 + wm * 64 + mtl * 16 + g;
            int col = c0 + wn * 32 + nt * 8 + 2 * t2;
            size_t o0 = ((size_t)b * 1024 + row) * 256 + col;
            size_t o1 = o0 + 8 * 256;
            float2 xv0 = *(const float2*)&x[o0];
            float2 xv1 = *(const float2*)&x[o1];
            float2 r0 = make_float2(xv0.x + acc[mtl][nt][0], xv0.y + acc[mtl][nt][1]);
            float2 r1 = make_float2(xv1.x + acc[mtl][nt][2], xv1.y + acc[mtl][nt][3]);
            *(float2*)&out[o0] = r0;
            *(float2*)&out[o1] = r1;
        }
    }
}

// ---------------- launch ----------------
extern "C" void kernel_launch(void* const* d_in, const int* in_sizes, int n_in,
                              void* d_out, int out_size) {
    const float* x      = (const float*)d_in[0];
    const float* emb_W  = (const float*)d_in[1];
    const float* emb_b  = (const float*)d_in[2];
    const float* attn_W = (const float*)d_in[3];
    const float* attn_b = (const float*)d_in[4];
    const float* thr_W  = (const float*)d_in[5];
    const float* thr_b  = (const float*)d_in[6];
    float* out = (float*)d_out;

    cudaFuncSetAttribute(emb_kernel, cudaFuncAttributeMaxDynamicSharedMemorySize, EMB_SMEM);
    cudaFuncSetAttribute(shortcut_kernel, cudaFuncAttributeMaxDynamicSharedMemorySize, SC_SMEM);
    cudaFuncSetAttribute(attn_A_kernel, cudaFuncAttributeMaxDynamicSharedMemorySize, ATTN_SMEM);

    prep_kernel<<<256, 256>>>(attn_W, emb_W);
    emb_kernel<<<BATCH * HW / 32, 256, EMB_SMEM>>>(x, emb_b);
    shortcut_kernel<<<BATCH * HW / 32, 256, SC_SMEM>>>(x, attn_b, thr_W, thr_b);
    attn_A_kernel<<<dim3(HW / 32, BATCH), 512, ATTN_SMEM>>>();
    bmm_kernel<<<dim3(CDIM / 128, HW / 128, BATCH), 256>>>(x, out);
}

// round 4
// speedup vs baseline: 2.7544x; 1.5187x over previous
#include <cuda_runtime.h>
#include <cuda_bf16.h>
#include <math.h>
#include <stdint.h>

#define BATCH 32
#define HW    1024
#define CDIM  256
#define FDIM  64

// ---------------- scratch (device globals; no allocations) ----------------
__device__ float g_sq[BATCH * HW];
__device__ float g_T[BATCH * HW];
__device__ __nv_bfloat16 g_Ehi[BATCH * HW * FDIM];       // 4 MB  [n][k]
__device__ __nv_bfloat16 g_Elo[BATCH * HW * FDIM];       // 4 MB
__device__ __nv_bfloat16 g_EhiT[BATCH * FDIM * HW];      // 4 MB  [b][k][n]
__device__ __nv_bfloat16 g_EloT[BATCH * FDIM * HW];      // 4 MB
__device__ __nv_bfloat16 g_xhi[BATCH * HW * CDIM];       // 16 MB
__device__ __nv_bfloat16 g_xlo[BATCH * HW * CDIM];       // 16 MB
__device__ __nv_bfloat16 g_SChi[BATCH * HW * CDIM];      // 16 MB
__device__ __nv_bfloat16 g_SClo[BATCH * HW * CDIM];      // 16 MB
__device__ __nv_bfloat16 g_Ahi[(size_t)BATCH * HW * HW]; // 64 MB
__device__ __nv_bfloat16 g_Alo[(size_t)BATCH * HW * HW]; // 64 MB
__device__ __nv_bfloat16 g_Wthi[CDIM * CDIM];            // attn_W^T split [cin][cout]
__device__ __nv_bfloat16 g_Wtlo[CDIM * CDIM];
__device__ float g_emb_Wt[CDIM * FDIM];

// ---------------- small helpers ----------------
__device__ __forceinline__ uint32_t smem_u32(const void* p) {
    return (uint32_t)__cvta_generic_to_shared(p);
}
__device__ __forceinline__ void cp16(uint32_t dst, const void* src) {
    asm volatile("cp.async.cg.shared.global [%0], [%1], 16;\n" :: "r"(dst), "l"(src));
}
__device__ __forceinline__ void cp_commit() { asm volatile("cp.async.commit_group;\n"); }
__device__ __forceinline__ void cp_wait1() { asm volatile("cp.async.wait_group 1;\n"); }
__device__ __forceinline__ void cp_wait0() { asm volatile("cp.async.wait_group 0;\n"); }
__device__ __forceinline__ void ldm_x4(uint32_t (&r)[4], uint32_t addr) {
    asm volatile("ldmatrix.sync.aligned.m8n8.x4.shared.b16 {%0,%1,%2,%3}, [%4];"
                 : "=r"(r[0]), "=r"(r[1]), "=r"(r[2]), "=r"(r[3]) : "r"(addr));
}
__device__ __forceinline__ void ldm_x4_t(uint32_t (&r)[4], uint32_t addr) {
    asm volatile("ldmatrix.sync.aligned.m8n8.x4.trans.shared.b16 {%0,%1,%2,%3}, [%4];"
                 : "=r"(r[0]), "=r"(r[1]), "=r"(r[2]), "=r"(r[3]) : "r"(addr));
}
__device__ __forceinline__ void mma16816(float (&d)[4], const uint32_t (&a)[4],
                                         uint32_t b0, uint32_t b1) {
    asm volatile("mma.sync.aligned.m16n8k16.row.col.f32.bf16.bf16.f32 "
                 "{%0,%1,%2,%3}, {%4,%5,%6,%7}, {%8,%9}, {%0,%1,%2,%3};"
                 : "+f"(d[0]), "+f"(d[1]), "+f"(d[2]), "+f"(d[3])
                 : "r"(a[0]), "r"(a[1]), "r"(a[2]), "r"(a[3]), "r"(b0), "r"(b1));
}
union BPack2 { __nv_bfloat16 h[2]; uint32_t u; };
union BPack4 { __nv_bfloat16 h[4]; uint2 u; };

// ---------------- prep: weight transposes + bf16 splits ----------------
__global__ void prep_kernel(const float* __restrict__ attn_W,
                            const float* __restrict__ emb_W) {
    int t = blockIdx.x * 256 + threadIdx.x;
    if (t < CDIM * CDIM) {
        int ci = t >> 8, co = t & 255;
        float v = attn_W[co * CDIM + ci];
        __nv_bfloat16 h = __float2bfloat16(v);
        g_Wthi[ci * CDIM + co] = h;
        g_Wtlo[ci * CDIM + co] = __float2bfloat16(v - __bfloat162float(h));
    }
    if (t < FDIM * CDIM) {
        int f = t >> 8, ci = t & 255;
        g_emb_Wt[ci * FDIM + f] = emb_W[f * CDIM + ci];
    }
}

// ---------------- x split kernel ----------------
__global__ __launch_bounds__(256) void xsplit_kernel(const float* __restrict__ x) {
    int i4 = blockIdx.x * 256 + threadIdx.x;        // over N/4
    const float4* x4 = (const float4*)x;
    float4 v = x4[i4];
    BPack4 ph, pl;
    float vv[4] = {v.x, v.y, v.z, v.w};
#pragma unroll
    for (int q = 0; q < 4; q++) {
        __nv_bfloat16 h = __float2bfloat16(vv[q]);
        ph.h[q] = h;
        pl.h[q] = __float2bfloat16(vv[q] - __bfloat162float(h));
    }
    ((uint2*)g_xhi)[i4] = ph.u;
    ((uint2*)g_xlo)[i4] = pl.u;
}

// ---------------- emb: x @ emb_W^T + b -> bf16 hi/lo (+transposed) + sq ----------------
#define EMB_SMEM ((32 * 256 + 256 * 64) * 4)
__global__ __launch_bounds__(256) void emb_kernel(const float* __restrict__ x,
                                                  const float* __restrict__ emb_b) {
    extern __shared__ float sm[];
    float* xs = sm;              // [32][256]
    float* we = sm + 32 * 256;   // [256][64]
    int tid = threadIdx.x;
    int row0 = blockIdx.x * 32;
    int bb = row0 >> 10, n0 = row0 & 1023;

    const float4* xg = (const float4*)(x + (size_t)row0 * CDIM);
    float4* xs4 = (float4*)xs;
    for (int i = tid; i < 32 * 64; i += 256) xs4[i] = xg[i];
    const float4* wg = (const float4*)g_emb_Wt;
    float4* we4 = (float4*)we;
    for (int i = tid; i < 256 * 16; i += 256) we4[i] = wg[i];
    __syncthreads();

    int w = tid >> 5, lane = tid & 31;
    int ig = w * 4, fg = lane * 2;
    float acc[4][2] = {};
#pragma unroll 4
    for (int c = 0; c < 256; c++) {
        float2 wv = *(const float2*)&we[c * 64 + fg];
#pragma unroll
        for (int q = 0; q < 4; q++) {
            float a = xs[(ig + q) * 256 + c];
            acc[q][0] = fmaf(a, wv.x, acc[q][0]);
            acc[q][1] = fmaf(a, wv.y, acc[q][1]);
        }
    }
    float b0 = emb_b[fg], b1 = emb_b[fg + 1];
    float e0r[4], e1r[4];
#pragma unroll
    for (int q = 0; q < 4; q++) {
        float e0 = acc[q][0] + b0, e1 = acc[q][1] + b1;
        e0r[q] = e0; e1r[q] = e1;
        int n = row0 + ig + q;
        BPack2 ph, pl;
        ph.h[0] = __float2bfloat16(e0);
        ph.h[1] = __float2bfloat16(e1);
        pl.h[0] = __float2bfloat16(e0 - __bfloat162float(ph.h[0]));
        pl.h[1] = __float2bfloat16(e1 - __bfloat162float(ph.h[1]));
        *(uint32_t*)&g_Ehi[(size_t)n * FDIM + fg] = ph.u;
        *(uint32_t*)&g_Elo[(size_t)n * FDIM + fg] = pl.u;
        float p = e0 * e0 + e1 * e1;
#pragma unroll
        for (int o = 16; o; o >>= 1) p += __shfl_xor_sync(0xffffffffu, p, o);
        if (lane == 0) g_sq[n] = p;
    }

    // transposed bf16 copies via smem staging: [64][33]
    __nv_bfloat16* st = (__nv_bfloat16*)sm;
    __syncthreads();
#pragma unroll
    for (int q = 0; q < 4; q++) {
        st[fg * 33 + ig + q] = __float2bfloat16(e0r[q]);
        st[(fg + 1) * 33 + ig + q] = __float2bfloat16(e1r[q]);
    }
    __syncthreads();
    for (int idx = tid; idx < 2048; idx += 256) {
        int k = idx >> 5, i2 = idx & 31;
        g_EhiT[(((size_t)bb * 64 + k) << 10) + n0 + i2] = st[k * 33 + i2];
    }
    __syncthreads();
#pragma unroll
    for (int q = 0; q < 4; q++) {
        float h0 = __bfloat162float(__float2bfloat16(e0r[q]));
        float h1 = __bfloat162float(__float2bfloat16(e1r[q]));
        st[fg * 33 + ig + q] = __float2bfloat16(e0r[q] - h0);
        st[(fg + 1) * 33 + ig + q] = __float2bfloat16(e1r[q] - h1);
    }
    __syncthreads();
    for (int idx = tid; idx < 2048; idx += 256) {
        int k = idx >> 5, i2 = idx & 31;
        g_EloT[(((size_t)bb * 64 + k) << 10) + n0 + i2] = st[k * 33 + i2];
    }
}

// ---------------- shortcut via tensor cores: SC = x @ W^T + b (3-term), plus T ----------------
__global__ __launch_bounds__(256) void shortcut_kernel(const float* __restrict__ attn_b,
                                                       const float* __restrict__ thr_W,
                                                       const float* __restrict__ thr_b) {
    __shared__ __nv_bfloat16 Asm[2][64][40];    // 10.2 KB
    __shared__ __nv_bfloat16 Bsm[2][32][264];   // 33.8 KB
    __shared__ float Tp[64];
    int tid = threadIdx.x, w = tid >> 5, lane = tid & 31;
    int m0 = blockIdx.x * 64;
    int lrow = lane & 7, q1 = (lane >> 3) & 1, q2 = lane >> 4;

    if (tid < 64) Tp[tid] = 0.0f;

    float acc[4][4][4];
#pragma unroll
    for (int a = 0; a < 4; a++)
#pragma unroll
        for (int n = 0; n < 4; n++)
#pragma unroll
            for (int r = 0; r < 4; r++) acc[a][n][r] = 0.0f;

#define SC_ISSUE(s, buf)                                                          \
    {                                                                             \
        int term_ = (s) >> 3, kc_ = (s) & 7;                                      \
        const __nv_bfloat16* Ap_ = (term_ == 1) ? g_xlo : g_xhi;                  \
        const __nv_bfloat16* Bp_ = (term_ == 2) ? g_Wtlo : g_Wthi;                \
        int ar_ = tid >> 2, aseg_ = tid & 3;                                      \
        cp16(smem_u32(&Asm[buf][ar_][aseg_ * 8]),                                 \
             Ap_ + (size_t)(m0 + ar_) * CDIM + kc_ * 32 + aseg_ * 8);             \
        for (int u_ = 0; u_ < 4; u_++) {                                          \
            int id_ = tid + u_ * 256;                                             \
            int br_ = id_ >> 5, bseg_ = id_ & 31;                                 \
            cp16(smem_u32(&Bsm[buf][br_][bseg_ * 8]),                             \
                 Bp_ + (size_t)(kc_ * 32 + br_) * CDIM + bseg_ * 8);              \
        }                                                                         \
        cp_commit();                                                              \
    }

    SC_ISSUE(0, 0);
    SC_ISSUE(1, 1);
    for (int s = 0; s < 24; s++) {
        if (s < 23) cp_wait1(); else cp_wait0();
        __syncthreads();
        int buf = s & 1;
#pragma unroll
        for (int kk = 0; kk < 2; kk++) {
            uint32_t af[4][4];
#pragma unroll
            for (int mt = 0; mt < 4; mt++)
                ldm_x4(af[mt], smem_u32(&Asm[buf][mt * 16 + lrow + q1 * 8][kk * 16 + q2 * 8]));
            uint32_t bfr[2][4];
#pragma unroll
            for (int ng = 0; ng < 2; ng++)
                ldm_x4_t(bfr[ng], smem_u32(&Bsm[buf][kk * 16 + lrow + q1 * 8][w * 32 + ng * 16 + q2 * 8]));
#pragma unroll
            for (int mt = 0; mt < 4; mt++)
#pragma unroll
                for (int nt = 0; nt < 4; nt++)
                    mma16816(acc[mt][nt], af[mt],
                             bfr[nt >> 1][(nt & 1) * 2], bfr[nt >> 1][(nt & 1) * 2 + 1]);
        }
        __syncthreads();
        if (s < 22) SC_ISSUE(s + 2, s & 1);
    }
#undef SC_ISSUE

    // epilogue: bias, bf16 hi/lo stores, T partials
    float pr0[4] = {}, pr1[4] = {};
#pragma unroll
    for (int nt = 0; nt < 4; nt++) {
        int c0 = w * 32 + nt * 8 + (lane & 3) * 2;
        float bb0 = attn_b[c0], bb1 = attn_b[c0 + 1];
        float tw0 = thr_W[c0], tw1 = thr_W[c0 + 1];
#pragma unroll
        for (int mt = 0; mt < 4; mt++) {
            int r0g = m0 + mt * 16 + (lane >> 2);
            float v00 = acc[mt][nt][0] + bb0, v01 = acc[mt][nt][1] + bb1;
            float v10 = acc[mt][nt][2] + bb0, v11 = acc[mt][nt][3] + bb1;
            BPack2 h, l;
            h.h[0] = __float2bfloat16(v00); h.h[1] = __float2bfloat16(v01);
            l.h[0] = __float2bfloat16(v00 - __bfloat162float(h.h[0]));
            l.h[1] = __float2bfloat16(v01 - __bfloat162float(h.h[1]));
            *(uint32_t*)&g_SChi[(size_t)r0g * CDIM + c0] = h.u;
            *(uint32_t*)&g_SClo[(size_t)r0g * CDIM + c0] = l.u;
            h.h[0] = __float2bfloat16(v10); h.h[1] = __float2bfloat16(v11);
            l.h[0] = __float2bfloat16(v10 - __bfloat162float(h.h[0]));
            l.h[1] = __float2bfloat16(v11 - __bfloat162float(h.h[1]));
            *(uint32_t*)&g_SChi[(size_t)(r0g + 8) * CDIM + c0] = h.u;
            *(uint32_t*)&g_SClo[(size_t)(r0g + 8) * CDIM + c0] = l.u;
            pr0[mt] += v00 * tw0 + v01 * tw1;
            pr1[mt] += v10 * tw0 + v11 * tw1;
        }
    }
#pragma unroll
    for (int mt = 0; mt < 4; mt++) {
        pr0[mt] += __shfl_xor_sync(0xffffffffu, pr0[mt], 1);
        pr0[mt] += __shfl_xor_sync(0xffffffffu, pr0[mt], 2);
        pr1[mt] += __shfl_xor_sync(0xffffffffu, pr1[mt], 1);
        pr1[mt] += __shfl_xor_sync(0xffffffffu, pr1[mt], 2);
        if ((lane & 3) == 0) {
            atomicAdd(&Tp[mt * 16 + (lane >> 2)], pr0[mt]);
            atomicAdd(&Tp[mt * 16 + (lane >> 2) + 8], pr1[mt]);
        }
    }
    __syncthreads();
    if (tid < 64) g_T[m0 + tid] = Tp[tid] + thr_b[0];
}

// ---------------- attention matrix kernel (tensor-core Gram + reg softmax) ----------------
#define S_PITCH 1044
#define OFF_S    0
#define OFF_EIH  133632
#define OFF_EIL  138240
#define OFF_BH   142848
#define OFF_BL   177664
#define OFF_TSH  212480
#define OFF_SQJ  216576
#define ATTN_SMEM 220672

__global__ __launch_bounds__(512) void attn_A_kernel() {
    extern __shared__ char smc[];
    float* S = (float*)(smc + OFF_S);                         // [32][1044]
    __nv_bfloat16* Eih = (__nv_bfloat16*)(smc + OFF_EIH);     // [32][72]
    __nv_bfloat16* Eil = (__nv_bfloat16*)(smc + OFF_EIL);
    __nv_bfloat16* BhS = (__nv_bfloat16*)(smc + OFF_BH);      // [2][64][136]
    __nv_bfloat16* BlS = (__nv_bfloat16*)(smc + OFF_BL);
    float* Tsh = (float*)(smc + OFF_TSH);
    float* Sqj = (float*)(smc + OFF_SQJ);

    int tid = threadIdx.x;
    int tile = blockIdx.x, b = blockIdx.y;
    int i0 = tile * 32;
    int base = b * HW;
    int w = tid >> 5, lane = tid & 31;
    int lrow = lane & 7, q1 = (lane >> 3) & 1, q2 = lane >> 4;
    int mt = w & 1, npair = w >> 1;

    // plain loads of Tsh / Sqj
    for (int i = tid; i < 1024; i += 512) {
        Tsh[i] = g_T[base + i];
        Sqj[i] = g_sq[base + i];
    }

#define AT_ISSUE(jc, buf)                                                         \
    {                                                                             \
        for (int u_ = 0; u_ < 4; u_++) {                                          \
            int id_ = tid + u_ * 512;                                             \
            int arr_ = id_ >> 10, rem_ = id_ & 1023;                              \
            int r_ = rem_ >> 4, seg_ = rem_ & 15;                                 \
            __nv_bfloat16* dst_ = (arr_ ? BlS : BhS) + (buf) * 8704 + r_ * 136 + seg_ * 8; \
            const __nv_bfloat16* src_ = (arr_ ? g_EloT : g_EhiT) +                \
                (((size_t)b * 64 + r_) << 10) + (jc) * 128 + seg_ * 8;            \
            cp16(smem_u32(dst_), src_);                                           \
        }                                                                         \
        cp_commit();                                                              \
    }

    // group 0: Ei hi/lo + chunk 0
    {
        int arr = tid >> 8, rem = tid & 255;
        int r = rem >> 3, seg = rem & 7;
        __nv_bfloat16* dst = (arr ? Eil : Eih) + r * 72 + seg * 8;
        const __nv_bfloat16* src = (arr ? g_Elo : g_Ehi) + (size_t)(base + i0 + r) * 64 + seg * 8;
        cp16(smem_u32(dst), src);
    }
    AT_ISSUE(0, 0);           // same group as Ei? No: AT_ISSUE commits; Ei cp joins this group.
    AT_ISSUE(1, 1);
    cp_wait1();
    __syncthreads();

    // hoisted A fragments
    uint32_t Ah[4][4], Al[4][4];
#pragma unroll
    for (int kc = 0; kc < 4; kc++) {
        ldm_x4(Ah[kc], smem_u32(&Eih[(mt * 16 + lrow + q1 * 8) * 72 + kc * 16 + q2 * 8]));
        ldm_x4(Al[kc], smem_u32(&Eil[(mt * 16 + lrow + q1 * 8) * 72 + kc * 16 + q2 * 8]));
    }

    // per-lane row constants
    int r0 = mt * 16 + (lane >> 2);
    int ig0 = i0 + r0, ig1 = ig0 + 8;
    int yi0 = ig0 >> 5, xi0 = ig0 & 31;
    int yi1 = ig1 >> 5, xi1 = ig1 & 31;
    float sqi0 = g_sq[base + ig0];
    float sqi1 = g_sq[base + ig1];

    // ---- Phase A ----
    for (int jc = 0; jc < 8; jc++) {
        if (jc >= 1) {
            if (jc < 7) cp_wait1(); else cp_wait0();
            __syncthreads();
        }
        int buf = jc & 1;
        float acc[2][4] = {};
#pragma unroll
        for (int kc = 0; kc < 4; kc++) {
            uint32_t bh[4];
            ldm_x4_t(bh, smem_u32(&BhS[buf * 8704 + (kc * 16 + lrow + q1 * 8) * 136 + npair * 16 + q2 * 8]));
            mma16816(acc[0], Ah[kc], bh[0], bh[1]);
            mma16816(acc[1], Ah[kc], bh[2], bh[3]);
            mma16816(acc[0], Al[kc], bh[0], bh[1]);
            mma16816(acc[1], Al[kc], bh[2], bh[3]);
            uint32_t bl[4];
            ldm_x4_t(bl, smem_u32(&BlS[buf * 8704 + (kc * 16 + lrow + q1 * 8) * 136 + npair * 16 + q2 * 8]));
            mma16816(acc[0], Ah[kc], bl[0], bl[1]);
            mma16816(acc[1], Ah[kc], bl[2], bl[3]);
        }
        int jb = jc * 128;
#pragma unroll
        for (int nt = 0; nt < 2; nt++) {
            int cA = npair * 16 + nt * 8 + (lane & 3) * 2;
            int j0 = jb + cA;
            int yj0 = j0 >> 5, xj0 = j0 & 31;
            int yj1 = (j0 + 1) >> 5, xj1 = (j0 + 1) & 31;
            float sq0 = Sqj[j0], sq1 = Sqj[j0 + 1];
            // row r0
            {
                float d2a = fmaxf(sqi0 + sq0 - 2.0f * acc[nt][0], 0.0f);
                float d2b = fmaxf(sqi0 + sq1 - 2.0f * acc[nt][1], 0.0f);
                int da = abs(yi0 - yj0) + abs(xi0 - xj0);
                int db = abs(yi0 - yj1) + abs(xi0 - xj1);
                float ma = (da <= 32) ? (float)da * (1.0f / 32.0f) : 0.0f;
                float mb = (db <= 32) ? (float)db * (1.0f / 32.0f) : 0.0f;
                float2 v = make_float2(__expf(-d2a) - 1.0f + ma, __expf(-d2b) - 1.0f + mb);
                *(float2*)&S[r0 * S_PITCH + j0] = v;
            }
            // row r0+8
            {
                float d2a = fmaxf(sqi1 + sq0 - 2.0f * acc[nt][2], 0.0f);
                float d2b = fmaxf(sqi1 + sq1 - 2.0f * acc[nt][3], 0.0f);
                int da = abs(yi1 - yj0) + abs(xi1 - xj0);
                int db = abs(yi1 - yj1) + abs(xi1 - xj1);
                float ma = (da <= 32) ? (float)da * (1.0f / 32.0f) : 0.0f;
                float mb = (db <= 32) ? (float)db * (1.0f / 32.0f) : 0.0f;
                float2 v = make_float2(__expf(-d2a) - 1.0f + ma, __expf(-d2b) - 1.0f + mb);
                *(float2*)&S[(r0 + 8) * S_PITCH + j0] = v;
            }
        }
        __syncthreads();
        if (jc < 6) AT_ISSUE(jc + 2, jc & 1);
    }
#undef AT_ISSUE

    // ---- Phase B: register-resident double softmax, 2 rows per warp ----
#pragma unroll
    for (int q = 0; q < 2; q++) {
        int r = w * 2 + q;
        float* Sr = S + r * S_PITCH;
        float v[32];
#pragma unroll
        for (int t = 0; t < 32; t++) v[t] = Sr[lane + t * 32];
        float m = -1e30f;
#pragma unroll
        for (int t = 0; t < 32; t++) m = fmaxf(m, v[t]);
#pragma unroll
        for (int o = 16; o; o >>= 1) m = fmaxf(m, __shfl_xor_sync(0xffffffffu, m, o));
        float s1 = 0.0f;
#pragma unroll
        for (int t = 0; t < 32; t++) { v[t] = __expf(v[t] - m); s1 += v[t]; }
#pragma unroll
        for (int o = 16; o; o >>= 1) s1 += __shfl_xor_sync(0xffffffffu, s1, o);
        float inv1 = 1.0f / s1;
        float m2 = 0.0f;
#pragma unroll
        for (int t = 0; t < 32; t++) {
            v[t] = fmaxf(v[t] * inv1 - Tsh[lane + t * 32], 0.0f);
            m2 = fmaxf(m2, v[t]);
        }
#pragma unroll
        for (int o = 16; o; o >>= 1) m2 = fmaxf(m2, __shfl_xor_sync(0xffffffffu, m2, o));
        float s2 = 0.0f;
#pragma unroll
        for (int t = 0; t < 32; t++) { v[t] = __expf(v[t] - m2); s2 += v[t]; }
#pragma unroll
        for (int o = 16; o; o >>= 1) s2 += __shfl_xor_sync(0xffffffffu, s2, o);
        float inv2 = 1.0f / s2;

        size_t Ab = ((size_t)b << 20) + (size_t)(i0 + r) * 1024;
#pragma unroll
        for (int t = 0; t < 32; t++) {
            int j = lane + t * 32;
            float val = v[t] * inv2;
            __nv_bfloat16 h = __float2bfloat16(val);
            g_Ahi[Ab + j] = h;
            g_Alo[Ab + j] = __float2bfloat16(val - __bfloat162float(h));
        }
    }
}

// ---------------- tensor-core bmm: out = x + A @ SC (3-term bf16 split) ----------------
__global__ __launch_bounds__(256) void bmm_kernel(const float* __restrict__ x,
                                                  float* __restrict__ out) {
    __shared__ __nv_bfloat16 As[2][128][40];   // 20 KB
    __shared__ __nv_bfloat16 Ss[2][32][136];   // 17 KB
    int tid = threadIdx.x, w = tid >> 5, lane = tid & 31;
    int ct = blockIdx.x, mtb = blockIdx.y, b = blockIdx.z;
    int i0 = mtb * 128, c0 = ct * 128;

    const __nv_bfloat16* Ahi = g_Ahi + ((size_t)b << 20) + (size_t)i0 * 1024;
    const __nv_bfloat16* Alo = g_Alo + ((size_t)b << 20) + (size_t)i0 * 1024;
    const __nv_bfloat16* Shi = g_SChi + ((size_t)b << 18) + c0;
    const __nv_bfloat16* Slo = g_SClo + ((size_t)b << 18) + c0;

    float acc[4][4][4];
#pragma unroll
    for (int a = 0; a < 4; a++)
#pragma unroll
        for (int n = 0; n < 4; n++)
#pragma unroll
            for (int r = 0; r < 4; r++) acc[a][n][r] = 0.0f;

    int wm = w >> 2, wn = w & 3;
    int lrow = lane & 7, q1 = (lane >> 3) & 1, q2 = lane >> 4;
    int ar0 = tid >> 2, aseg = tid & 3;
    int sr0 = tid >> 4, sseg = tid & 15;

#define ISSUE(cc)                                                                 \
    {                                                                             \
        int term_ = (cc) >> 5, jc_ = (cc) & 31, buf_ = (cc) & 1;                  \
        const __nv_bfloat16* Ap_ = (term_ == 1) ? Alo : Ahi;                      \
        const __nv_bfloat16* Sp_ = (term_ == 2) ? Slo : Shi;                      \
        cp16(smem_u32(&As[buf_][ar0][aseg * 8]),                                  \
             Ap_ + (size_t)ar0 * 1024 + jc_ * 32 + aseg * 8);                     \
        cp16(smem_u32(&As[buf_][ar0 + 64][aseg * 8]),                             \
             Ap_ + (size_t)(ar0 + 64) * 1024 + jc_ * 32 + aseg * 8);              \
        cp16(smem_u32(&Ss[buf_][sr0][sseg * 8]),                                  \
             Sp_ + (size_t)(jc_ * 32 + sr0) * 256 + sseg * 8);                    \
        cp16(smem_u32(&Ss[buf_][sr0 + 16][sseg * 8]),                             \
             Sp_ + (size_t)(jc_ * 32 + sr0 + 16) * 256 + sseg * 8);               \
        cp_commit();                                                              \
    }

    ISSUE(0);
    for (int cc = 0; cc < 96; cc++) {
        if (cc < 95) {
            ISSUE(cc + 1);
            cp_wait1();
        } else {
            cp_wait0();
        }
        __syncthreads();
        int buf = cc & 1;
#pragma unroll
        for (int kk = 0; kk < 2; kk++) {
            uint32_t af[4][4];
#pragma unroll
            for (int mtl = 0; mtl < 4; mtl++) {
                int row = wm * 64 + mtl * 16 + lrow + q1 * 8;
                int col = kk * 16 + q2 * 8;
                ldm_x4(af[mtl], smem_u32(&As[buf][row][col]));
            }
            uint32_t bfr[2][4];
#pragma unroll
            for (int ng = 0; ng < 2; ng++) {
                int row = kk * 16 + lrow + q1 * 8;
                int col = wn * 32 + ng * 16 + q2 * 8;
                ldm_x4_t(bfr[ng], smem_u32(&Ss[buf][row][col]));
            }
#pragma unroll
            for (int mtl = 0; mtl < 4; mtl++)
#pragma unroll
                for (int nt = 0; nt < 4; nt++)
                    mma16816(acc[mtl][nt], af[mtl],
                             bfr[nt >> 1][(nt & 1) * 2], bfr[nt >> 1][(nt & 1) * 2 + 1]);
        }
        __syncthreads();
    }
#undef ISSUE

    int g = lane >> 2, t2 = lane & 3;
#pragma unroll
    for (int mtl = 0; mtl < 4; mtl++) {
#pragma unroll
        for (int nt = 0; nt < 4; nt++) {
            int row = i0 + wm * 64 + mtl * 16 + g;
            int col = c0 + wn * 32 + nt * 8 + 2 * t2;
            size_t o0 = ((size_t)b * 1024 + row) * 256 + col;
            size_t o1 = o0 + 8 * 256;
            float2 xv0 = *(const float2*)&x[o0];
            float2 xv1 = *(const float2*)&x[o1];
            *(float2*)&out[o0] = make_float2(xv0.x + acc[mtl][nt][0], xv0.y + acc[mtl][nt][1]);
            *(float2*)&out[o1] = make_float2(xv1.x + acc[mtl][nt][2], xv1.y + acc[mtl][nt][3]);
        }
    }
}

// ---------------- launch ----------------
extern "C" void kernel_launch(void* const* d_in, const int* in_sizes, int n_in,
                              void* d_out, int out_size) {
    const float* x      = (const float*)d_in[0];
    const float* emb_W  = (const float*)d_in[1];
    const float* emb_b  = (const float*)d_in[2];
    const float* attn_W = (const float*)d_in[3];
    const float* attn_b = (const float*)d_in[4];
    const float* thr_W  = (const float*)d_in[5];
    const float* thr_b  = (const float*)d_in[6];
    float* out = (float*)d_out;

    cudaFuncSetAttribute(emb_kernel, cudaFuncAttributeMaxDynamicSharedMemorySize, EMB_SMEM);
    cudaFuncSetAttribute(attn_A_kernel, cudaFuncAttributeMaxDynamicSharedMemorySize, ATTN_SMEM);

    prep_kernel<<<256, 256>>>(attn_W, emb_W);
    xsplit_kernel<<<BATCH * HW * CDIM / 4 / 256, 256>>>(x);
    emb_kernel<<<BATCH * HW / 32, 256, EMB_SMEM>>>(x, emb_b);
    shortcut_kernel<<<BATCH * HW / 64, 256>>>(attn_b, thr_W, thr_b);
    attn_A_kernel<<<dim3(HW / 32, BATCH), 512, ATTN_SMEM>>>();
    bmm_kernel<<<dim3(CDIM / 128, HW / 128, BATCH), 256>>>(x, out);
}